// round 1
// baseline (speedup 1.0000x reference)
#include <cuda_runtime.h>

// CrossInferenceBlock: T=S=256, F=1024, A=256
//  theta = batch @ a_w + a_b          (65536 x 256)
//  phi   = batch @ b_w + b_b          (65536 x 256)
//  feats = batch @ g_w + g_b          (65536 x 1024)
//  attn[t]    = theta[t] @ phi[t]^T   (256 x 256, batched over t)
//  out[t]     = (attn[t] @ feats[t]) / 512
//
// All dims are multiples of the 128x128x8 tile -> no bounds checks.

#define TT 256
#define SS 256
#define FF 1024
#define AA 256

// Scratch (static device globals; allocation-free per harness rules)
__device__ float g_theta[(size_t)TT * SS * AA];   //  64 MB
__device__ float g_phi  [(size_t)TT * SS * AA];   //  64 MB
__device__ float g_feats[(size_t)TT * SS * FF];   // 256 MB
__device__ float g_attn [(size_t)TT * SS * SS];   //  64 MB

// Generic tiled SGEMM:
//   C[b] = scale * (A[b] (MxK) @ op(B[b]) + bias)
//   TRANS_B=false: B is K x N row-major.  TRANS_B=true: B is N x K row-major (C = A B^T).
// BM=BN=128, BK=8, 256 threads, 8x8 accumulators per thread (2x2 quads of 4).
template <bool TRANS_B, bool HAS_BIAS>
__global__ __launch_bounds__(256) void sgemm_kernel(
    const float* __restrict__ A, const float* __restrict__ B,
    const float* __restrict__ bias, float* __restrict__ C,
    int M, int N, int K, float scale,
    long strideA, long strideB, long strideC)
{
    __shared__ float As[8][128];
    __shared__ float Bs[8][128];

    const int tid = threadIdx.x;
    const int tx = tid & 15;        // 0..15 -> column quads
    const int ty = tid >> 4;        // 0..15 -> row quads

    const long b = blockIdx.z;
    A += b * strideA;
    B += b * strideB;
    C += b * strideC;

    const int block_row = blockIdx.y * 128;
    const int block_col = blockIdx.x * 128;

    float acc[8][8];
#pragma unroll
    for (int i = 0; i < 8; i++)
#pragma unroll
        for (int j = 0; j < 8; j++) acc[i][j] = 0.0f;

    for (int k0 = 0; k0 < K; k0 += 8) {
        // ---- load A tile (128 rows x 8 k) transposed into As[k][m] ----
        {
            const int r = tid >> 1;            // 0..127
            const int c = (tid & 1) * 4;       // 0 or 4
            const float4 v = *(const float4*)(A + (long)(block_row + r) * K + k0 + c);
            As[c + 0][r] = v.x;
            As[c + 1][r] = v.y;
            As[c + 2][r] = v.z;
            As[c + 3][r] = v.w;
        }
        // ---- load B tile into Bs[k][n] ----
        if (TRANS_B) {
            const int r = tid >> 1;            // n index 0..127
            const int c = (tid & 1) * 4;       // k offset 0 or 4
            const float4 v = *(const float4*)(B + (long)(block_col + r) * K + k0 + c);
            Bs[c + 0][r] = v.x;
            Bs[c + 1][r] = v.y;
            Bs[c + 2][r] = v.z;
            Bs[c + 3][r] = v.w;
        } else {
            const int r = tid >> 5;            // k 0..7
            const int c = (tid & 31) * 4;      // n 0..124
            const float4 v = *(const float4*)(B + (long)(k0 + r) * N + block_col + c);
            *(float4*)&Bs[r][c] = v;
        }
        __syncthreads();

#pragma unroll
        for (int kk = 0; kk < 8; kk++) {
            float a[8], bb[8];
            *(float4*)(a)      = *(const float4*)&As[kk][ty * 4];
            *(float4*)(a + 4)  = *(const float4*)&As[kk][64 + ty * 4];
            *(float4*)(bb)     = *(const float4*)&Bs[kk][tx * 4];
            *(float4*)(bb + 4) = *(const float4*)&Bs[kk][64 + tx * 4];
#pragma unroll
            for (int i = 0; i < 8; i++)
#pragma unroll
                for (int j = 0; j < 8; j++)
                    acc[i][j] = fmaf(a[i], bb[j], acc[i][j]);
        }
        __syncthreads();
    }

    // ---- epilogue: rows ty*4..+3 and 64+ty*4..+3; cols tx*4..+3 and 64+tx*4..+3 ----
#pragma unroll
    for (int i = 0; i < 8; i++) {
        const int row = block_row + ((i < 4) ? (ty * 4 + i) : (60 + ty * 4 + i));
        float* Crow = C + (long)row * N;
#pragma unroll
        for (int jh = 0; jh < 2; jh++) {
            const int col = block_col + jh * 64 + tx * 4;
            float4 v;
            v.x = acc[i][jh * 4 + 0];
            v.y = acc[i][jh * 4 + 1];
            v.z = acc[i][jh * 4 + 2];
            v.w = acc[i][jh * 4 + 3];
            if (HAS_BIAS) {
                const float4 bv = *(const float4*)(bias + col);
                v.x += bv.x; v.y += bv.y; v.z += bv.z; v.w += bv.w;
            }
            v.x *= scale; v.y *= scale; v.z *= scale; v.w *= scale;
            *(float4*)(Crow + col) = v;
        }
    }
}

extern "C" void kernel_launch(void* const* d_in, const int* in_sizes, int n_in,
                              void* d_out, int out_size)
{
    const float* batch = (const float*)d_in[0];   // (65536, 1024)
    const float* a_w   = (const float*)d_in[1];   // (1024, 256)
    const float* a_b   = (const float*)d_in[2];   // (256,)
    const float* b_w   = (const float*)d_in[3];   // (1024, 256)
    const float* b_b   = (const float*)d_in[4];   // (256,)
    const float* g_w   = (const float*)d_in[5];   // (1024, 1024)
    const float* g_b   = (const float*)d_in[6];   // (1024,)
    float* out = (float*)d_out;                   // (256, 256, 1024)

    void *p_theta, *p_phi, *p_feats, *p_attn;
    cudaGetSymbolAddress(&p_theta, g_theta);
    cudaGetSymbolAddress(&p_phi,   g_phi);
    cudaGetSymbolAddress(&p_feats, g_feats);
    cudaGetSymbolAddress(&p_attn,  g_attn);
    float* theta = (float*)p_theta;
    float* phi   = (float*)p_phi;
    float* feats = (float*)p_feats;
    float* attn  = (float*)p_attn;

    const int M = TT * SS;          // 65536
    const dim3 block(256);

    // theta = batch @ a_w + a_b : M x 256, K=1024
    sgemm_kernel<false, true><<<dim3(AA / 128, M / 128, 1), block>>>(
        batch, a_w, a_b, theta, M, AA, FF, 1.0f, 0, 0, 0);

    // phi = batch @ b_w + b_b
    sgemm_kernel<false, true><<<dim3(AA / 128, M / 128, 1), block>>>(
        batch, b_w, b_b, phi, M, AA, FF, 1.0f, 0, 0, 0);

    // feats = batch @ g_w + g_b : M x 1024, K=1024
    sgemm_kernel<false, true><<<dim3(FF / 128, M / 128, 1), block>>>(
        batch, g_w, g_b, feats, M, FF, FF, 1.0f, 0, 0, 0);

    // attn[t] = theta[t] @ phi[t]^T : batched (z = t), 256x256, K=256
    sgemm_kernel<true, false><<<dim3(SS / 128, SS / 128, TT), block>>>(
        theta, phi, nullptr, attn, SS, SS, AA, 1.0f,
        (long)SS * AA, (long)SS * AA, (long)SS * SS);

    // out[t] = (attn[t] @ feats[t]) / (S + T) : batched, 256x1024, K=256
    sgemm_kernel<false, false><<<dim3(FF / 128, SS / 128, TT), block>>>(
        attn, feats, nullptr, out, SS, FF, SS, 1.0f / (float)(SS + TT),
        (long)SS * SS, (long)SS * FF, (long)SS * FF);
}

// round 3
// speedup vs baseline: 2.7406x; 2.7406x over previous
#include <cuda_runtime.h>
#include <cuda_bf16.h>
#include <cstdint>

// CrossInferenceBlock, bf16x3 split-precision via portable mma.sync (HMMA).
// (tcgen05 is unavailable: harness compiles PTX at compute_103, no 'a' features.)
//
//  theta = batch @ a_w + a_b            (65536 x 256)   -> bf16 hi/lo
//  phi   = batch @ b_w + b_b            (65536 x 256)   -> bf16 hi/lo
//  featsT[t][f][s] = (batch @ g_w + g_b)^T per t        -> bf16 hi/lo
//  attn[t] = theta[t] @ phi[t]^T        (256 x 256)     -> bf16 hi/lo
//  out[t]  = (attn[t] @ feats[t]) / 512                 -> fp32
// Every GEMM: C[m][n] = sum_k A[m,k] * B[n,k], A,B K-major bf16 (hi+lo).

#define TT 256
#define SS 256
#define FF 1024
#define AA 256

// ------------------------------- static scratch (bf16 splits)
__device__ __align__(16) __nv_bfloat16 g_batchH[67108864];
__device__ __align__(16) __nv_bfloat16 g_batchL[67108864];
__device__ __align__(16) __nv_bfloat16 g_thetaH[16777216];
__device__ __align__(16) __nv_bfloat16 g_thetaL[16777216];
__device__ __align__(16) __nv_bfloat16 g_phiH[16777216];
__device__ __align__(16) __nv_bfloat16 g_phiL[16777216];
__device__ __align__(16) __nv_bfloat16 g_attnH[16777216];
__device__ __align__(16) __nv_bfloat16 g_attnL[16777216];
__device__ __align__(16) __nv_bfloat16 g_featsTH[67108864];
__device__ __align__(16) __nv_bfloat16 g_featsTL[67108864];
__device__ __align__(16) __nv_bfloat16 g_aTH[262144];
__device__ __align__(16) __nv_bfloat16 g_aTL[262144];
__device__ __align__(16) __nv_bfloat16 g_bTH[262144];
__device__ __align__(16) __nv_bfloat16 g_bTL[262144];
__device__ __align__(16) __nv_bfloat16 g_gTH[1048576];
__device__ __align__(16) __nv_bfloat16 g_gTL[1048576];

// ------------------------------- helpers
__device__ __forceinline__ uint32_t smem_u32(const void* p) {
    uint32_t a;
    asm("{ .reg .u64 t; cvta.to.shared.u64 t, %1; cvt.u32.u64 %0, t; }"
        : "=r"(a) : "l"(p));
    return a;
}

__device__ __forceinline__ void cpasync16(uint32_t s, const void* g) {
    asm volatile("cp.async.cg.shared.global [%0], [%1], 16;" :: "r"(s), "l"(g));
}
__device__ __forceinline__ void cp_commit() {
    asm volatile("cp.async.commit_group;");
}
template <int N>
__device__ __forceinline__ void cp_wait() {
    asm volatile("cp.async.wait_group %0;" :: "n"(N));
}

__device__ __forceinline__ uint4 ldsm4(uint32_t a) {
    uint4 r;
    asm volatile("ldmatrix.sync.aligned.m8n8.x4.shared.b16 {%0,%1,%2,%3}, [%4];"
                 : "=r"(r.x), "=r"(r.y), "=r"(r.z), "=r"(r.w) : "r"(a));
    return r;
}

__device__ __forceinline__ void mma_bf16(float* c, const uint4& a,
                                         uint32_t b0, uint32_t b1) {
    asm volatile(
        "mma.sync.aligned.m16n8k16.row.col.f32.bf16.bf16.f32 "
        "{%0,%1,%2,%3},{%4,%5,%6,%7},{%8,%9},{%0,%1,%2,%3};"
        : "+f"(c[0]), "+f"(c[1]), "+f"(c[2]), "+f"(c[3])
        : "r"(a.x), "r"(a.y), "r"(a.z), "r"(a.w), "r"(b0), "r"(b1));
}

// pack (v0,v1) -> bf16x2 hi + bf16x2 lo (lo = residual)
__device__ __forceinline__ void split2(float v0, float v1, uint32_t& h, uint32_t& l) {
    asm("cvt.rn.bf16x2.f32 %0, %1, %2;" : "=r"(h) : "f"(v1), "f"(v0));
    float h0 = __uint_as_float(h << 16);
    float h1 = __uint_as_float(h & 0xFFFF0000u);
    asm("cvt.rn.bf16x2.f32 %0, %1, %2;" : "=r"(l) : "f"(v1 - h1), "f"(v0 - h0));
}

// ------------------------------- converters
__global__ void split_kernel(const float* __restrict__ in,
                             __nv_bfloat16* __restrict__ oh,
                             __nv_bfloat16* __restrict__ ol, long n) {
    long i = ((long)blockIdx.x * blockDim.x + threadIdx.x) * 4;
    if (i >= n) return;
    float4 v = *(const float4*)(in + i);
    uint32_t h0, l0, h1, l1;
    split2(v.x, v.y, h0, l0);
    split2(v.z, v.w, h1, l1);
    *(uint2*)(oh + i) = make_uint2(h0, h1);
    *(uint2*)(ol + i) = make_uint2(l0, l1);
}

__global__ void transpose_split_kernel(const float* __restrict__ in,
                                       __nv_bfloat16* __restrict__ oh,
                                       __nv_bfloat16* __restrict__ ol,
                                       int R, int C) {
    __shared__ float t[32][33];
    int c0 = blockIdx.x * 32, r0 = blockIdx.y * 32;
    int x = threadIdx.x, y = threadIdx.y;  // 32 x 8
#pragma unroll
    for (int i = 0; i < 32; i += 8)
        t[y + i][x] = in[(long)(r0 + y + i) * C + c0 + x];
    __syncthreads();
#pragma unroll
    for (int i = 0; i < 32; i += 8) {
        float v = t[x][y + i];
        __nv_bfloat16 hb = __float2bfloat16(v);
        float lo = v - __bfloat162float(hb);
        long o = (long)(c0 + y + i) * R + r0 + x;
        oh[o] = hb;
        ol[o] = __float2bfloat16(lo);
    }
}

// ------------------------------- GEMM: BM=128 BN=128 BK=64, 2-stage cp.async
static constexpr int STAGE   = 65536;
static constexpr int OFF_AH  = 0;
static constexpr int OFF_AL  = 16384;
static constexpr int OFF_BH  = 32768;
static constexpr int OFF_BL  = 49152;
static constexpr int SMEMB   = 2 * STAGE;   // 128 KB

// BMODE: 0 none, 1 bias per output col, 2 bias per output row
template <int BMODE, bool SPLIT>
__global__ void __launch_bounds__(256) gemm_hmma(
    const __nv_bfloat16* __restrict__ Ah, const __nv_bfloat16* __restrict__ Al,
    const __nv_bfloat16* __restrict__ Bh, const __nv_bfloat16* __restrict__ Bl,
    const float* __restrict__ bias,
    __nv_bfloat16* __restrict__ Ch, __nv_bfloat16* __restrict__ Cl,
    float* __restrict__ Cf,
    int N, int K, float scale, long sA, long sB, long sC)
{
    extern __shared__ __align__(1024) char smem[];
    const uint32_t sbase = smem_u32(smem);
    const int tid = threadIdx.x;
    const int wid = tid >> 5, lane = tid & 31;
    const long z = blockIdx.z;
    const int block_row = blockIdx.y * 128;
    const int block_col = blockIdx.x * 128;

    const __nv_bfloat16* Az_h = Ah + z * sA + (long)block_row * K;
    const __nv_bfloat16* Az_l = Al + z * sA + (long)block_row * K;
    const __nv_bfloat16* Bz_h = Bh + z * sB + (long)block_col * K;
    const __nv_bfloat16* Bz_l = Bl + z * sB + (long)block_col * K;

    // cp.async mapping: 1024 16B chunks per 16KB tile, 4 per thread
    int lrowv[4], lcov[4];
    uint32_t lsov[4];
#pragma unroll
    for (int i = 0; i < 4; i++) {
        int q = tid + i * 256;
        int row = q >> 3;
        int cb = (q & 7) * 16;
        lrowv[i] = row;
        lcov[i] = (q & 7) * 8;
        lsov[i] = (uint32_t)(row * 128 + (cb ^ ((row & 7) << 4)));
    }

    auto load_stage = [&](int buf, int k0) {
        uint32_t sb = sbase + buf * STAGE;
#pragma unroll
        for (int i = 0; i < 4; i++) {
            long go = (long)lrowv[i] * K + k0 + lcov[i];
            cpasync16(sb + OFF_AH + lsov[i], Az_h + go);
            cpasync16(sb + OFF_AL + lsov[i], Az_l + go);
            cpasync16(sb + OFF_BH + lsov[i], Bz_h + go);
            cpasync16(sb + OFF_BL + lsov[i], Bz_l + go);
        }
    };

    // warp tiling: 2(m) x 4(n) warps, 64x32 per warp
    const int wm = wid & 1, wn = wid >> 1;
    const int arow = wm * 64 + (lane & 15);
    const uint32_t asel = ((lane >> 4) & 1) * 16;
    const uint32_t axr = (uint32_t)((arow & 7) << 4);
    const int brow = wn * 32 + (lane & 7) + ((lane & 16) ? 8 : 0);
    const uint32_t bsel = (lane & 8) ? 16u : 0u;
    const uint32_t bxr = (uint32_t)((brow & 7) << 4);

    float acc[4][4][4];
#pragma unroll
    for (int a = 0; a < 4; a++)
#pragma unroll
        for (int b = 0; b < 4; b++)
#pragma unroll
            for (int c = 0; c < 4; c++) acc[a][b][c] = 0.0f;

    const int NT = K >> 6;
    load_stage(0, 0);
    cp_commit();

    for (int it = 0; it < NT; it++) {
        if (it + 1 < NT) load_stage((it + 1) & 1, (it + 1) << 6);
        cp_commit();
        if (it + 1 < NT) cp_wait<1>(); else cp_wait<0>();
        __syncthreads();

        const uint32_t sb = sbase + (it & 1) * STAGE;
#pragma unroll
        for (int kk = 0; kk < 4; kk++) {
            uint4 ah[4], al4[4], bhf[2], blf[2];
#pragma unroll
            for (int mi = 0; mi < 4; mi++) {
                uint32_t ro = (uint32_t)((arow + mi * 16) * 128) +
                              (((uint32_t)(kk * 32) + asel) ^ axr);
                ah[mi] = ldsm4(sb + OFF_AH + ro);
                al4[mi] = ldsm4(sb + OFF_AL + ro);
            }
#pragma unroll
            for (int pi = 0; pi < 2; pi++) {
                uint32_t ro = (uint32_t)((brow + pi * 16) * 128) +
                              (((uint32_t)(kk * 32) + bsel) ^ bxr);
                bhf[pi] = ldsm4(sb + OFF_BH + ro);
                blf[pi] = ldsm4(sb + OFF_BL + ro);
            }
#pragma unroll
            for (int mi = 0; mi < 4; mi++) {
#pragma unroll
                for (int ni = 0; ni < 4; ni++) {
                    const int pi = ni >> 1;
                    const bool up = ni & 1;
                    uint32_t bh0 = up ? bhf[pi].z : bhf[pi].x;
                    uint32_t bh1 = up ? bhf[pi].w : bhf[pi].y;
                    uint32_t bl0 = up ? blf[pi].z : blf[pi].x;
                    uint32_t bl1 = up ? blf[pi].w : blf[pi].y;
                    mma_bf16(acc[mi][ni], ah[mi], bh0, bh1);   // hi*hi
                    mma_bf16(acc[mi][ni], ah[mi], bl0, bl1);   // hi*lo
                    mma_bf16(acc[mi][ni], al4[mi], bh0, bh1);  // lo*hi
                }
            }
        }
        __syncthreads();
    }

    // ------------------ epilogue
    const int grow0 = block_row + wm * 64 + (lane >> 2);
    const int gcol0 = block_col + wn * 32 + (lane & 3) * 2;
#pragma unroll
    for (int mi = 0; mi < 4; mi++) {
#pragma unroll
        for (int ni = 0; ni < 4; ni++) {
            float v0 = acc[mi][ni][0], v1 = acc[mi][ni][1];
            float v2 = acc[mi][ni][2], v3 = acc[mi][ni][3];
            const int r0 = grow0 + mi * 16, r1 = r0 + 8;
            const int cc = gcol0 + ni * 8;
            if (BMODE == 1) {
                float b0 = bias[cc], b1 = bias[cc + 1];
                v0 += b0; v1 += b1; v2 += b0; v3 += b1;
            }
            if (BMODE == 2) {
                float ba = bias[r0], bb = bias[r1];
                v0 += ba; v1 += ba; v2 += bb; v3 += bb;
            }
            v0 *= scale; v1 *= scale; v2 *= scale; v3 *= scale;
            const long o0 = z * sC + (long)r0 * N + cc;
            const long o1 = z * sC + (long)r1 * N + cc;
            if (SPLIT) {
                uint32_t h, l;
                split2(v0, v1, h, l);
                *(uint32_t*)(Ch + o0) = h;
                *(uint32_t*)(Cl + o0) = l;
                split2(v2, v3, h, l);
                *(uint32_t*)(Ch + o1) = h;
                *(uint32_t*)(Cl + o1) = l;
            } else {
                *(float2*)(Cf + o0) = make_float2(v0, v1);
                *(float2*)(Cf + o1) = make_float2(v2, v3);
            }
        }
    }
}

// ------------------------------- launcher
extern "C" void kernel_launch(void* const* d_in, const int* in_sizes, int n_in,
                              void* d_out, int out_size)
{
    const float* batch = (const float*)d_in[0];   // (65536, 1024)
    const float* a_w   = (const float*)d_in[1];   // (1024, 256)
    const float* a_b   = (const float*)d_in[2];
    const float* b_w   = (const float*)d_in[3];
    const float* b_b   = (const float*)d_in[4];
    const float* g_w   = (const float*)d_in[5];   // (1024, 1024)
    const float* g_b   = (const float*)d_in[6];
    float* out = (float*)d_out;                   // (256, 256, 1024)

    void* p;
#define SYM(v, s) cudaGetSymbolAddress(&p, s); __nv_bfloat16* v = (__nv_bfloat16*)p
    SYM(batchH, g_batchH);  SYM(batchL, g_batchL);
    SYM(thetaH, g_thetaH);  SYM(thetaL, g_thetaL);
    SYM(phiH,   g_phiH);    SYM(phiL,   g_phiL);
    SYM(attnH,  g_attnH);   SYM(attnL,  g_attnL);
    SYM(featsTH, g_featsTH); SYM(featsTL, g_featsTL);
    SYM(aTH, g_aTH); SYM(aTL, g_aTL);
    SYM(bTH, g_bTH); SYM(bTL, g_bTL);
    SYM(gTH, g_gTH); SYM(gTL, g_gTL);
#undef SYM

    static bool attr_done = false;
    if (!attr_done) {
        cudaFuncSetAttribute(gemm_hmma<1, true>,
                             cudaFuncAttributeMaxDynamicSharedMemorySize, SMEMB);
        cudaFuncSetAttribute(gemm_hmma<2, true>,
                             cudaFuncAttributeMaxDynamicSharedMemorySize, SMEMB);
        cudaFuncSetAttribute(gemm_hmma<0, true>,
                             cudaFuncAttributeMaxDynamicSharedMemorySize, SMEMB);
        cudaFuncSetAttribute(gemm_hmma<0, false>,
                             cudaFuncAttributeMaxDynamicSharedMemorySize, SMEMB);
        attr_done = true;
    }

    // converts
    split_kernel<<<65536, 256>>>(batch, batchH, batchL, (long)67108864);
    const dim3 tb(32, 8);
    transpose_split_kernel<<<dim3(AA / 32, FF / 32), tb>>>(a_w, aTH, aTL, FF, AA);
    transpose_split_kernel<<<dim3(AA / 32, FF / 32), tb>>>(b_w, bTH, bTL, FF, AA);
    transpose_split_kernel<<<dim3(FF / 32, FF / 32), tb>>>(g_w, gTH, gTL, FF, FF);

    // theta = batch @ a_w + a_b : M=65536, N=256, K=1024
    gemm_hmma<1, true><<<dim3(2, 512, 1), 256, SMEMB>>>(
        batchH, batchL, aTH, aTL, a_b, thetaH, thetaL, nullptr,
        256, 1024, 1.0f, 0, 0, 0);

    // phi = batch @ b_w + b_b
    gemm_hmma<1, true><<<dim3(2, 512, 1), 256, SMEMB>>>(
        batchH, batchL, bTH, bTL, b_b, phiH, phiL, nullptr,
        256, 1024, 1.0f, 0, 0, 0);

    // featsT[t][f][s]: per t, M=1024(f), N=256(s), K=1024; A=gT shared, bias per row(f)
    gemm_hmma<2, true><<<dim3(2, 8, 256), 256, SMEMB>>>(
        gTH, gTL, batchH, batchL, g_b, featsTH, featsTL, nullptr,
        256, 1024, 1.0f, 0, (long)256 * 1024, (long)1024 * 256);

    // attn[t] = theta[t] @ phi[t]^T : per t, M=N=256, K=256
    gemm_hmma<0, true><<<dim3(2, 2, 256), 256, SMEMB>>>(
        thetaH, thetaL, phiH, phiL, nullptr, attnH, attnL, nullptr,
        256, 256, 1.0f, 65536, 65536, 65536);

    // out[t] = (attn[t] @ feats[t]) / 512 : per t, M=256, N=1024(f), K=256
    gemm_hmma<0, false><<<dim3(8, 2, 256), 256, SMEMB>>>(
        attnH, attnL, featsTH, featsTL, nullptr, nullptr, nullptr, out,
        1024, 256, 1.0f / (float)(SS + TT), 65536, (long)1024 * 256,
        (long)256 * 1024);
}